// round 1
// baseline (speedup 1.0000x reference)
#include <cuda_runtime.h>
#include <math.h>
#include <stdint.h>

// Problem constants
#define Bc 64
#define Sc 256
#define Hc 1024
#define Ec 512
#define Vc 10000
#define Tc 64
#define Dc 512
#define KXc 2048   // x_cat per direction: E (512) + H (1024) + D (512)
#define G4c 2048   // 4*D gate width

// ---------------- scratch (device globals; no allocation allowed) ----------
__device__ float g_Uk[(size_t)Bc * Sc * Hc];        // 64 MB: Uk[b,s,k]
__device__ float g_qW[Bc * Hc];                     // query @ Wa^T
__device__ float g_sc[Bc * Sc];                     // attention scores
__device__ float g_w[Bc * Sc];                      // softmax weights
__device__ float g_ctx[Bc * Hc];                    // context vectors
__device__ float g_x[2 * Bc * KXc];                 // packed LSTM inputs (per dir)
__device__ float g_Wcat[2 * (size_t)G4c * KXc];     // 32 MB: [Wih | Whh] per dir
__device__ float g_bcat[2 * G4c];                   // bih + bhh per dir
__device__ float g_G[2 * Bc * G4c];                 // raw gates per dir
__device__ float g_h[2 * Bc * Dc];                  // current h (dir-major = output layout)
__device__ float g_c[2 * Bc * Dc];                  // current c
__device__ float g_hcat[Bc * Hc];                   // [h_f | h_b] per batch row

// ---------------- generic C = A * B^T (+bias) SGEMM -------------------------
// A: [M,K] row-major, Bm: [N,K] row-major, C: [M x N] with row stride ldc.
template <int BM, int BN, int BK, int TM, int TN>
__global__ void __launch_bounds__((BM / TM) * (BN / TN))
gemm_abt(const float* __restrict__ A, const float* __restrict__ Bm,
         const float* __restrict__ bias, float* __restrict__ C,
         int M, int N, int K, int ldc)
{
    constexpr int NTH = (BM / TM) * (BN / TN);
    __shared__ float As[BK][BM + 4];
    __shared__ float Bs[BK][BN + 4];
    const int tid = threadIdx.x;
    const int m0 = blockIdx.y * BM;
    const int n0 = blockIdx.x * BN;
    const int tx = tid % (BN / TN);
    const int ty = tid / (BN / TN);

    float acc[TM][TN];
#pragma unroll
    for (int i = 0; i < TM; i++)
#pragma unroll
        for (int j = 0; j < TN; j++) acc[i][j] = 0.f;

    for (int k0 = 0; k0 < K; k0 += BK) {
#pragma unroll
        for (int i = tid; i < BM * BK; i += NTH) {
            int m = i / BK, k = i % BK;
            int gm = m0 + m;
            As[k][m] = (gm < M) ? A[(size_t)gm * K + k0 + k] : 0.f;
        }
#pragma unroll
        for (int i = tid; i < BN * BK; i += NTH) {
            int n = i / BK, k = i % BK;
            int gn = n0 + n;
            Bs[k][n] = (gn < N) ? Bm[(size_t)gn * K + k0 + k] : 0.f;
        }
        __syncthreads();
#pragma unroll
        for (int k = 0; k < BK; k++) {
            float a[TM], b[TN];
#pragma unroll
            for (int i = 0; i < TM; i++) a[i] = As[k][ty * TM + i];
#pragma unroll
            for (int j = 0; j < TN; j++) b[j] = Bs[k][tx * TN + j];
#pragma unroll
            for (int i = 0; i < TM; i++)
#pragma unroll
                for (int j = 0; j < TN; j++)
                    acc[i][j] = fmaf(a[i], b[j], acc[i][j]);
        }
        __syncthreads();
    }
#pragma unroll
    for (int i = 0; i < TM; i++) {
        int m = m0 + ty * TM + i;
        if (m >= M) continue;
#pragma unroll
        for (int j = 0; j < TN; j++) {
            int n = n0 + tx * TN + j;
            if (n >= N) continue;
            float v = acc[i][j];
            if (bias) v += bias[n];
            C[(size_t)m * ldc + n] = v;
        }
    }
}

// ---------------- weight packing: Wcat = [Wih | Whh], bcat = bih + bhh ------
__global__ void pack_w_kernel(const float* __restrict__ Wih, const float* __restrict__ Whh,
                              const float* __restrict__ bih, const float* __restrict__ bhh,
                              int dir)
{
    size_t base = (size_t)dir * G4c * KXc;
    size_t total = (size_t)G4c * KXc;
    for (size_t i = (size_t)blockIdx.x * blockDim.x + threadIdx.x; i < total;
         i += (size_t)gridDim.x * blockDim.x) {
        int g = (int)(i >> 11);      // /2048
        int k = (int)(i & 2047);
        g_Wcat[base + i] = (k < (Ec + Hc)) ? Wih[(size_t)g * (Ec + Hc) + k]
                                           : Whh[(size_t)g * Dc + (k - (Ec + Hc))];
    }
    int i0 = blockIdx.x * blockDim.x + threadIdx.x;
    if (i0 < G4c) g_bcat[dir * G4c + i0] = bih[i0] + bhh[i0];
}

// ---------------- state init / writeback -----------------------------------
__global__ void init_state_kernel(const float* __restrict__ h0, const float* __restrict__ c0)
{
    int i = blockIdx.x * blockDim.x + threadIdx.x;
    if (i < 2 * Bc * Dc) {
        g_h[i] = h0[i];
        g_c[i] = c0[i];
        int dir = i / (Bc * Dc);
        int r = i % (Bc * Dc);
        int b = r / Dc, d = r % Dc;
        g_hcat[b * Hc + dir * Dc + d] = h0[i];
    }
}

__global__ void write_state_kernel(float* __restrict__ h_out, float* __restrict__ c_out)
{
    int i = blockIdx.x * blockDim.x + threadIdx.x;
    if (i < 2 * Bc * Dc) {
        h_out[i] = g_h[i];
        c_out[i] = g_c[i];
    }
}

// ---------------- attention: scores, softmax, context -----------------------
// One warp per (b,s): sc[b,s] = sum_h Va[h] * tanh(qW[b,h] + Uk[b,s,h])
__global__ void attn_scores_kernel(const float* __restrict__ Va,
                                   const unsigned char* __restrict__ mask)
{
    int warp = threadIdx.x >> 5, lane = threadIdx.x & 31;
    int bs = blockIdx.x * 8 + warp;
    int b = bs >> 8;  // S = 256
    const float* u = g_Uk + (size_t)bs * Hc;
    const float* q = g_qW + b * Hc;
    float acc = 0.f;
#pragma unroll 8
    for (int h = lane; h < Hc; h += 32)
        acc += Va[h] * tanhf(q[h] + u[h]);
#pragma unroll
    for (int o = 16; o; o >>= 1) acc += __shfl_xor_sync(0xffffffffu, acc, o);
    if (lane == 0) g_sc[bs] = mask[bs] ? -INFINITY : acc;
}

__global__ void softmax_kernel(float* __restrict__ attn_out, int t)
{
    __shared__ float red[Sc];
    int b = blockIdx.x, s = threadIdx.x;
    float v = g_sc[b * Sc + s];
    red[s] = v;
    __syncthreads();
    for (int o = 128; o; o >>= 1) {
        if (s < o) red[s] = fmaxf(red[s], red[s + o]);
        __syncthreads();
    }
    float mx = red[0];
    __syncthreads();
    float e = expf(v - mx);
    red[s] = e;
    __syncthreads();
    for (int o = 128; o; o >>= 1) {
        if (s < o) red[s] += red[s + o];
        __syncthreads();
    }
    float wv = e / red[0];
    g_w[b * Sc + s] = wv;
    attn_out[((size_t)b * Tc + t) * Sc + s] = wv;
}

__global__ void context_kernel(const float* __restrict__ enc)
{
    __shared__ float ws[Sc];
    int b = blockIdx.y;
    int h = blockIdx.x * blockDim.x + threadIdx.x;
    for (int s = threadIdx.x; s < Sc; s += blockDim.x) ws[s] = g_w[b * Sc + s];
    __syncthreads();
    const float* e = enc + (size_t)b * Sc * Hc + h;
    float acc = 0.f;
#pragma unroll 8
    for (int s = 0; s < Sc; s++) acc = fmaf(ws[s], e[(size_t)s * Hc], acc);
    g_ctx[b * Hc + h] = acc;
}

// ---------------- LSTM input packing + cell update ---------------------------
__global__ void pack_x_kernel(const float* __restrict__ emb, const int* __restrict__ target,
                              const int* __restrict__ sos, int t)
{
    int b = blockIdx.x, dir = blockIdx.y;
    int tok = (t == 0) ? (*sos) : target[b * Tc + t - 1];
    const float* eb = emb + (size_t)tok * Ec;
    float* x = g_x + ((size_t)dir * Bc + b) * KXc;
    for (int i = threadIdx.x; i < KXc; i += blockDim.x) {
        float v;
        if (i < Ec) v = eb[i];
        else if (i < Ec + Hc) v = g_ctx[b * Hc + (i - Ec)];
        else v = g_h[((size_t)dir * Bc + b) * Dc + (i - Ec - Hc)];
        x[i] = v;
    }
}

__device__ __forceinline__ float sigf(float x) { return 1.f / (1.f + expf(-x)); }

__global__ void lstm_update_kernel()
{
    int b = blockIdx.x, dir = blockIdx.y, d = threadIdx.x;  // 512 threads
    const float* g = g_G + ((size_t)dir * Bc + b) * G4c;
    size_t idx = ((size_t)dir * Bc + b) * Dc + d;
    float i_ = g[d], f_ = g[Dc + d], gg = g[2 * Dc + d], o_ = g[3 * Dc + d];
    float c = g_c[idx];
    float c2 = sigf(f_) * c + sigf(i_) * tanhf(gg);
    float h2 = sigf(o_) * tanhf(c2);
    g_c[idx] = c2;
    g_h[idx] = h2;
    g_hcat[b * Hc + dir * Dc + d] = h2;
}

// ---------------- launch -----------------------------------------------------
extern "C" void kernel_launch(void* const* d_in, const int* in_sizes, int n_in,
                              void* d_out, int out_size)
{
    const float* enc    = (const float*)d_in[0];
    const float* h0     = (const float*)d_in[1];
    const float* c0     = (const float*)d_in[2];
    const int*   target = (const int*)d_in[3];
    const unsigned char* mask = (const unsigned char*)d_in[4];
    const int*   sos    = (const int*)d_in[5];
    const float* emb    = (const float*)d_in[6];
    const float* Wa     = (const float*)d_in[7];
    const float* Ua     = (const float*)d_in[8];
    const float* Va     = (const float*)d_in[9];
    const float* outW   = (const float*)d_in[10];
    const float* outb   = (const float*)d_in[11];
    const float* Wih_f  = (const float*)d_in[12];
    const float* Whh_f  = (const float*)d_in[13];
    const float* bih_f  = (const float*)d_in[14];
    const float* bhh_f  = (const float*)d_in[15];
    const float* Wih_b  = (const float*)d_in[16];
    const float* Whh_b  = (const float*)d_in[17];
    const float* bih_b  = (const float*)d_in[18];
    const float* bhh_b  = (const float*)d_in[19];

    // Output layout: decoder_outputs [B,T,V] | h [2,B,D] | c [2,B,D] | attentions [B,T,S]
    float* dec_out  = (float*)d_out;
    float* h_out    = dec_out + (size_t)Bc * Tc * Vc;
    float* c_out    = h_out + 2 * Bc * Dc;
    float* attn_out = c_out + 2 * Bc * Dc;

    // Resolve device-symbol addresses (pure lookup; capture-safe, no stream ops)
    void* p;
    cudaGetSymbolAddress(&p, g_Uk);   float* Uk   = (float*)p;
    cudaGetSymbolAddress(&p, g_qW);   float* qW   = (float*)p;
    cudaGetSymbolAddress(&p, g_x);    float* xbuf = (float*)p;
    cudaGetSymbolAddress(&p, g_Wcat); float* Wc   = (float*)p;
    cudaGetSymbolAddress(&p, g_bcat); float* bc   = (float*)p;
    cudaGetSymbolAddress(&p, g_G);    float* Gb   = (float*)p;
    cudaGetSymbolAddress(&p, g_hcat); float* hcat = (float*)p;

    // Once-per-launch prep (deterministic; weights are constant across steps)
    pack_w_kernel<<<1024, 256>>>(Wih_f, Whh_f, bih_f, bhh_f, 0);
    pack_w_kernel<<<1024, 256>>>(Wih_b, Whh_b, bih_b, bhh_b, 1);
    init_state_kernel<<<(2 * Bc * Dc + 255) / 256, 256>>>(h0, c0);

    // Uk = enc @ Ua^T : M=B*S=16384, N=H, K=H
    gemm_abt<128, 64, 16, 8, 4><<<dim3(Hc / 64, (Bc * Sc) / 128), 256>>>(
        enc, Ua, nullptr, Uk, Bc * Sc, Hc, Hc, Hc);

    for (int t = 0; t < Tc; t++) {
        // qW = hcat(prev) @ Wa^T
        gemm_abt<64, 64, 16, 4, 4><<<dim3(Hc / 64, 1), 256>>>(
            hcat, Wa, nullptr, qW, Bc, Hc, Hc, Hc);
        attn_scores_kernel<<<(Bc * Sc) / 8, 256>>>(Va, mask);
        softmax_kernel<<<Bc, Sc>>>(attn_out, t);
        context_kernel<<<dim3(Hc / 256, Bc), 256>>>(enc);
        pack_x_kernel<<<dim3(Bc, 2), 256>>>(emb, target, sos, t);
        // gates per direction: [64,2048] @ [2048,2048]^T + bias
        gemm_abt<64, 64, 16, 4, 4><<<dim3(G4c / 64, 1), 256>>>(
            xbuf, Wc, bc, Gb, Bc, G4c, KXc, G4c);
        gemm_abt<64, 64, 16, 4, 4><<<dim3(G4c / 64, 1), 256>>>(
            xbuf + (size_t)Bc * KXc, Wc + (size_t)G4c * KXc, bc + G4c,
            Gb + (size_t)Bc * G4c, Bc, G4c, KXc, G4c);
        lstm_update_kernel<<<dim3(Bc, 2), Dc>>>();
        // logits = hcat(new) @ outW^T + outb, written straight into d_out[b, t, :]
        gemm_abt<64, 64, 16, 4, 4><<<dim3((Vc + 63) / 64, 1), 256>>>(
            hcat, outW, outb, dec_out + (size_t)t * Vc, Bc, Vc, Hc, Tc * Vc);
    }

    write_state_kernel<<<(2 * Bc * Dc + 255) / 256, 256>>>(h_out, c_out);
}

// round 2
// speedup vs baseline: 3.0348x; 3.0348x over previous
#include <cuda_runtime.h>
#include <math.h>
#include <stdint.h>

#define Bc 64
#define Sc 256
#define Hc 1024
#define Ec 512
#define Vc 10000
#define Tc 64
#define Dc 512
#define KGc 1536   // gates GEMM K: ctx(1024) + h(512)
#define G4c 2048   // 4*D

// ----------------------------- scratch ---------------------------------
__device__ __align__(256) float g_Uk[(size_t)Bc * Sc * Hc];          // 64 MB
__device__ __align__(256) float g_Xemb[(size_t)Tc * Bc * Ec];        // 8 MB
__device__ __align__(256) float g_Gemb[2 * (size_t)Tc * Bc * G4c];   // 64 MB
__device__ __align__(256) float g_Wg[2 * (size_t)G4c * KGc];         // 24 MB
__device__ __align__(256) float g_bsum[2 * G4c];
__device__ __align__(256) float g_xcat[2 * Bc * KGc];                // [dir][b][ctx|h]
__device__ __align__(256) float g_hcat[Bc * Hc];                     // [b][dirf|dirb]
__device__ __align__(256) float g_c[2 * Bc * Dc];
__device__ __align__(256) float g_qWp[4 * Bc * Hc];                  // splitK partials
__device__ __align__(256) float g_Gp[2 * 2 * Bc * G4c];              // [z][dir][b][2048]
__device__ __align__(256) float g_sc[Bc * Sc];

__device__ __forceinline__ float fast_tanh(float x) {
    float y; asm("tanh.approx.f32 %0, %1;" : "=f"(y) : "f"(x)); return y;
}
__device__ __forceinline__ float fast_sig(float x) {
    return 0.5f * fast_tanh(0.5f * x) + 0.5f;
}

// ----------------------------- GEMM ------------------------------------
// C[m,n] (+bias) = sum_k A[m,k] * B[n,k]; optional batch (grid.y) and
// split-K (grid.z writes partials at z*partStride). kchunk multiple of BK.
template <int BM, int BN, int BK, int TM, int TN>
__global__ void __launch_bounds__((BM / TM) * (BN / TN))
gemm_abt(const float* __restrict__ A, int lda,
         const float* __restrict__ B, int ldb,
         const float* __restrict__ bias, float* __restrict__ C, long long ldc,
         int M, int N, int kchunk, int batchCount,
         long long sA, long long sB, long long sC, long long partStride)
{
    constexpr int NTH = (BM / TM) * (BN / TN);
    __shared__ float As[BK][BM + 8];
    __shared__ float Bs[BK][BN + 8];
    const int tid = threadIdx.x;
    const int batch = blockIdx.y % batchCount;
    const int mtile = blockIdx.y / batchCount;
    A += (size_t)batch * sA;
    B += (size_t)batch * sB;
    C += (size_t)batch * sC + (size_t)blockIdx.z * partStride;
    const int m0 = mtile * BM;
    const int n0 = blockIdx.x * BN;
    const int kbeg = blockIdx.z * kchunk;
    const int tx = tid % (BN / TN);
    const int ty = tid / (BN / TN);

    float acc[TM][TN];
#pragma unroll
    for (int i = 0; i < TM; i++)
#pragma unroll
        for (int j = 0; j < TN; j++) acc[i][j] = 0.f;

    for (int k0 = kbeg; k0 < kbeg + kchunk; k0 += BK) {
#pragma unroll
        for (int f = tid; f < BM * BK / 4; f += NTH) {
            int m = f / (BK / 4), kq = f % (BK / 4);
            int gm = m0 + m;
            float4 v = make_float4(0.f, 0.f, 0.f, 0.f);
            if (gm < M)
                v = *reinterpret_cast<const float4*>(A + (size_t)gm * lda + k0 + kq * 4);
            As[kq * 4 + 0][m] = v.x; As[kq * 4 + 1][m] = v.y;
            As[kq * 4 + 2][m] = v.z; As[kq * 4 + 3][m] = v.w;
        }
#pragma unroll
        for (int f = tid; f < BN * BK / 4; f += NTH) {
            int n = f / (BK / 4), kq = f % (BK / 4);
            int gn = n0 + n;
            float4 v = make_float4(0.f, 0.f, 0.f, 0.f);
            if (gn < N)
                v = *reinterpret_cast<const float4*>(B + (size_t)gn * ldb + k0 + kq * 4);
            Bs[kq * 4 + 0][n] = v.x; Bs[kq * 4 + 1][n] = v.y;
            Bs[kq * 4 + 2][n] = v.z; Bs[kq * 4 + 3][n] = v.w;
        }
        __syncthreads();
#pragma unroll
        for (int k = 0; k < BK; k++) {
            float a[TM], b[TN];
#pragma unroll
            for (int i = 0; i < TM; i++) a[i] = As[k][ty * TM + i];
#pragma unroll
            for (int j = 0; j < TN; j++) b[j] = Bs[k][tx * TN + j];
#pragma unroll
            for (int i = 0; i < TM; i++)
#pragma unroll
                for (int j = 0; j < TN; j++)
                    acc[i][j] = fmaf(a[i], b[j], acc[i][j]);
        }
        __syncthreads();
    }
#pragma unroll
    for (int i = 0; i < TM; i++) {
        int m = m0 + ty * TM + i;
        if (m >= M) continue;
#pragma unroll
        for (int j = 0; j < TN; j++) {
            int n = n0 + tx * TN + j;
            if (n >= N) continue;
            float v = acc[i][j];
            if (bias) v += bias[n];
            C[(size_t)m * ldc + n] = v;
        }
    }
}

// ------------------------ pre-loop kernels ------------------------------
__global__ void pack_wg_kernel(const float* __restrict__ Wih_f, const float* __restrict__ Whh_f,
                               const float* __restrict__ bih_f, const float* __restrict__ bhh_f,
                               const float* __restrict__ Wih_b, const float* __restrict__ Whh_b,
                               const float* __restrict__ bih_b, const float* __restrict__ bhh_b)
{
    int dir = blockIdx.y;
    const float* Wih = dir ? Wih_b : Wih_f;
    const float* Whh = dir ? Whh_b : Whh_f;
    const float* bih = dir ? bih_b : bih_f;
    const float* bhh = dir ? bhh_b : bhh_f;
    size_t base = (size_t)dir * G4c * KGc;
    size_t total = (size_t)G4c * KGc;
    for (size_t i = (size_t)blockIdx.x * blockDim.x + threadIdx.x; i < total;
         i += (size_t)gridDim.x * blockDim.x) {
        int g = (int)(i / KGc);
        int j = (int)(i % KGc);
        g_Wg[base + i] = (j < Hc) ? Wih[(size_t)g * (Ec + Hc) + Ec + j]
                                  : Whh[(size_t)g * Dc + (j - Hc)];
    }
    int i0 = blockIdx.x * blockDim.x + threadIdx.x;
    if (i0 < G4c) g_bsum[dir * G4c + i0] = bih[i0] + bhh[i0];
}

__global__ void gather_emb_kernel(const float* __restrict__ emb, const int* __restrict__ target,
                                  const int* __restrict__ sos)
{
    int row = blockIdx.x;            // t*64 + b
    int t = row >> 6, b = row & 63;
    int tok = (t == 0) ? (*sos) : target[b * Tc + t - 1];
    const float4* src = reinterpret_cast<const float4*>(emb + (size_t)tok * Ec);
    float4* dst = reinterpret_cast<float4*>(g_Xemb + (size_t)row * Ec);
    dst[threadIdx.x] = src[threadIdx.x];   // 128 threads x float4 = 512
}

__global__ void init_state_kernel(const float* __restrict__ h0, const float* __restrict__ c0)
{
    int i = blockIdx.x * blockDim.x + threadIdx.x;
    if (i < 2 * Bc * Dc) {
        g_c[i] = c0[i];
        int dir = i / (Bc * Dc);
        int r = i % (Bc * Dc);
        int b = r / Dc, d = r % Dc;
        float h = h0[i];
        g_hcat[b * Hc + dir * Dc + d] = h;
        g_xcat[((size_t)dir * Bc + b) * KGc + Hc + d] = h;
    }
}

__global__ void write_state_kernel(float* __restrict__ h_out, float* __restrict__ c_out)
{
    int i = blockIdx.x * blockDim.x + threadIdx.x;
    if (i < 2 * Bc * Dc) {
        int dir = i / (Bc * Dc);
        int r = i % (Bc * Dc);
        int b = r / Dc, d = r % Dc;
        h_out[i] = g_hcat[b * Hc + dir * Dc + d];
        c_out[i] = g_c[i];
    }
}

// ------------------------ per-step kernels ------------------------------
// grid (32, 64): 8 s-values per block (warp each); sums qW split-K partials.
__global__ void __launch_bounds__(256) attn_scores_kernel(const float* __restrict__ Va,
                                                          const unsigned char* __restrict__ mask)
{
    __shared__ float qs[Hc];
    __shared__ float va[Hc];
    const int b = blockIdx.y;
    const int tid = threadIdx.x;
    for (int h = tid; h < Hc; h += 256) {
        qs[h] = g_qWp[b * Hc + h] + g_qWp[Bc * Hc + b * Hc + h] +
                g_qWp[2 * Bc * Hc + b * Hc + h] + g_qWp[3 * Bc * Hc + b * Hc + h];
        va[h] = Va[h];
    }
    __syncthreads();
    const int warp = tid >> 5, lane = tid & 31;
    const int s = blockIdx.x * 8 + warp;
    const float* u = g_Uk + ((size_t)b * Sc + s) * Hc;
    float acc = 0.f;
#pragma unroll 8
    for (int h = lane; h < Hc; h += 32)
        acc += va[h] * fast_tanh(qs[h] + u[h]);
#pragma unroll
    for (int o = 16; o; o >>= 1) acc += __shfl_xor_sync(0xffffffffu, acc, o);
    if (lane == 0) g_sc[b * Sc + s] = mask[b * Sc + s] ? -INFINITY : acc;
}

// grid (4, 64): softmax (redundant per h-chunk) + context slice; writes both
// directions' xcat ctx slots and the attention output.
__global__ void __launch_bounds__(256) smctx_kernel(const float* __restrict__ enc,
                                                    float* __restrict__ attn_out, int t)
{
    __shared__ float red[256];
    __shared__ float w[256];
    const int b = blockIdx.y, hc = blockIdx.x, tid = threadIdx.x;
    float v = g_sc[b * Sc + tid];
    red[tid] = v;
    __syncthreads();
    for (int o = 128; o; o >>= 1) {
        if (tid < o) red[tid] = fmaxf(red[tid], red[tid + o]);
        __syncthreads();
    }
    float mx = red[0];
    __syncthreads();
    float e = __expf(v - mx);
    red[tid] = e;
    __syncthreads();
    for (int o = 128; o; o >>= 1) {
        if (tid < o) red[tid] += red[tid + o];
        __syncthreads();
    }
    float wv = e / red[0];
    w[tid] = wv;
    __syncthreads();
    if (hc == 0) attn_out[((size_t)b * Tc + t) * Sc + tid] = wv;

    const int h = hc * 256 + tid;
    const float* ep = enc + (size_t)b * Sc * Hc + h;
    float acc = 0.f;
#pragma unroll 8
    for (int s = 0; s < Sc; s++) acc = fmaf(w[s], ep[(size_t)s * Hc], acc);
    g_xcat[(size_t)b * KGc + h] = acc;
    g_xcat[((size_t)Bc + b) * KGc + h] = acc;
}

// grid (64, 2) x 512: reduce gate partials + Gemb, update c/h, scatter h.
__global__ void __launch_bounds__(512) lstm_update_kernel(int t)
{
    const int b = blockIdx.x, dir = blockIdx.y, d = threadIdx.x;
    const size_t ge = ((size_t)dir * Tc * Bc + t * Bc + b) * G4c;
    const size_t p0 = ((size_t)dir * Bc + b) * G4c;            // z=0
    const size_t p1 = (size_t)2 * Bc * G4c + p0;               // z=1
    float gi = g_Gemb[ge + d]            + g_Gp[p0 + d]            + g_Gp[p1 + d];
    float gf = g_Gemb[ge + Dc + d]       + g_Gp[p0 + Dc + d]       + g_Gp[p1 + Dc + d];
    float gg = g_Gemb[ge + 2 * Dc + d]   + g_Gp[p0 + 2 * Dc + d]   + g_Gp[p1 + 2 * Dc + d];
    float go = g_Gemb[ge + 3 * Dc + d]   + g_Gp[p0 + 3 * Dc + d]   + g_Gp[p1 + 3 * Dc + d];
    const size_t ci = ((size_t)dir * Bc + b) * Dc + d;
    float c2 = fast_sig(gf) * g_c[ci] + fast_sig(gi) * fast_tanh(gg);
    float h2 = fast_sig(go) * fast_tanh(c2);
    g_c[ci] = c2;
    g_hcat[b * Hc + dir * Dc + d] = h2;
    g_xcat[((size_t)dir * Bc + b) * KGc + Hc + d] = h2;
}

// ------------------------------ launch ----------------------------------
extern "C" void kernel_launch(void* const* d_in, const int* in_sizes, int n_in,
                              void* d_out, int out_size)
{
    const float* enc    = (const float*)d_in[0];
    const float* h0     = (const float*)d_in[1];
    const float* c0     = (const float*)d_in[2];
    const int*   target = (const int*)d_in[3];
    const unsigned char* mask = (const unsigned char*)d_in[4];
    const int*   sos    = (const int*)d_in[5];
    const float* emb    = (const float*)d_in[6];
    const float* Wa     = (const float*)d_in[7];
    const float* Ua     = (const float*)d_in[8];
    const float* Va     = (const float*)d_in[9];
    const float* outW   = (const float*)d_in[10];
    const float* outb   = (const float*)d_in[11];
    const float* Wih_f  = (const float*)d_in[12];
    const float* Whh_f  = (const float*)d_in[13];
    const float* bih_f  = (const float*)d_in[14];
    const float* bhh_f  = (const float*)d_in[15];
    const float* Wih_b  = (const float*)d_in[16];
    const float* Whh_b  = (const float*)d_in[17];
    const float* bih_b  = (const float*)d_in[18];
    const float* bhh_b  = (const float*)d_in[19];

    float* dec_out  = (float*)d_out;
    float* h_out    = dec_out + (size_t)Bc * Tc * Vc;
    float* c_out    = h_out + 2 * Bc * Dc;
    float* attn_out = c_out + 2 * Bc * Dc;

    void* p;
    cudaGetSymbolAddress(&p, g_Uk);   float* Uk   = (float*)p;
    cudaGetSymbolAddress(&p, g_Xemb); float* Xemb = (float*)p;
    cudaGetSymbolAddress(&p, g_Gemb); float* Gemb = (float*)p;
    cudaGetSymbolAddress(&p, g_Wg);   float* Wg   = (float*)p;
    cudaGetSymbolAddress(&p, g_bsum); float* bsum = (float*)p;
    cudaGetSymbolAddress(&p, g_xcat); float* xcat = (float*)p;
    cudaGetSymbolAddress(&p, g_hcat); float* hcat = (float*)p;
    cudaGetSymbolAddress(&p, g_qWp);  float* qWp  = (float*)p;
    cudaGetSymbolAddress(&p, g_Gp);   float* Gp   = (float*)p;

    // ---- pre-loop (parallel-rich, one time) ----
    pack_wg_kernel<<<dim3(512, 2), 256>>>(Wih_f, Whh_f, bih_f, bhh_f,
                                          Wih_b, Whh_b, bih_b, bhh_b);
    gather_emb_kernel<<<Tc * Bc, 128>>>(emb, target, sos);
    init_state_kernel<<<(2 * Bc * Dc + 255) / 256, 256>>>(h0, c0);

    // Uk = enc @ Ua^T : [16384,1024] x [1024,1024]^T
    gemm_abt<128, 64, 32, 8, 4><<<dim3(Hc / 64, (Bc * Sc) / 128, 1), 256>>>(
        enc, Hc, Ua, Hc, nullptr, Uk, Hc, Bc * Sc, Hc, Hc, 1, 0, 0, 0, 0);

    // Gemb[dir] = Xemb @ Wih_dir[:, :E]^T + (bih+bhh) : [4096,2048], K=512
    gemm_abt<128, 64, 32, 8, 4><<<dim3(G4c / 64, (Tc * Bc) / 128, 1), 256>>>(
        Xemb, Ec, Wih_f, Ec + Hc, bsum, Gemb, G4c, Tc * Bc, G4c, Ec, 1, 0, 0, 0, 0);
    gemm_abt<128, 64, 32, 8, 4><<<dim3(G4c / 64, (Tc * Bc) / 128, 1), 256>>>(
        Xemb, Ec, Wih_b, Ec + Hc, bsum + G4c, Gemb + (size_t)Tc * Bc * G4c, G4c,
        Tc * Bc, G4c, Ec, 1, 0, 0, 0, 0);

    // ---- serial decode loop ----
    for (int t = 0; t < Tc; t++) {
        // qW partials = hcat @ Wa^T, split-K 4 -> 128 blocks
        gemm_abt<64, 32, 32, 4, 2><<<dim3(Hc / 32, 1, 4), 256>>>(
            hcat, Hc, Wa, Hc, nullptr, qWp, Hc, Bc, Hc, Hc / 4, 1, 0, 0, 0,
            (long long)Bc * Hc);
        attn_scores_kernel<<<dim3(Sc / 8, Bc), 256>>>(Va, mask);
        smctx_kernel<<<dim3(Hc / 256, Bc), 256>>>(enc, attn_out, t);
        // gates partials: [ctx|h]_dir @ Wg_dir^T, batch=2 dirs, split-K 2 -> 128 blocks
        gemm_abt<64, 64, 32, 4, 4><<<dim3(G4c / 64, 2, 2), 256>>>(
            xcat, KGc, Wg, KGc, nullptr, Gp, G4c, Bc, G4c, KGc / 2, 2,
            (long long)Bc * KGc, (long long)G4c * KGc, (long long)Bc * G4c,
            (long long)2 * Bc * G4c);
        lstm_update_kernel<<<dim3(Bc, 2), Dc>>>(t);
        // logits = hcat @ outW^T + outb -> dec_out[:, t, :]
        gemm_abt<64, 64, 32, 4, 4><<<dim3((Vc + 63) / 64, 1, 1), 256>>>(
            hcat, Hc, outW, Hc, outb, dec_out + (size_t)t * Vc, (long long)Tc * Vc,
            Bc, Vc, Hc, 1, 0, 0, 0, 0);
    }

    write_state_kernel<<<(2 * Bc * Dc + 255) / 256, 256>>>(h_out, c_out);
}